// round 9
// baseline (speedup 1.0000x reference)
#include <cuda_runtime.h>
#include <cstdint>
typedef unsigned long long ull;

#define NN 100000
#define NE 1600000
#define DD 128
#define CAP 128

// -------- scratch (device globals: no allocation allowed) --------
__device__ __align__(256) float g_agg[(size_t)NN * DD];
__device__ __align__(256) float g_h[(size_t)NN * DD];
__device__ int g_cnt[NN];
__device__ int g_adj[(size_t)NN * CAP];
__device__ int g_is64;
// W pre-split to tf32 hi/lo, layout [mat][col][k] (natural), fp32-bit words
__device__ unsigned g_Whi[4 * 16384];
__device__ unsigned g_Wlo[4 * 16384];

__device__ __forceinline__ unsigned tf32_hi(float x) {
    unsigned h; asm("cvt.rna.tf32.f32 %0, %1;" : "=r"(h) : "f"(x)); return h;
}

// -------- init: zero counts; detect edge dtype --------
__global__ void k_init(const unsigned int* __restrict__ e) {
    int i = blockIdx.x * blockDim.x + threadIdx.x;
    if (i < NN) g_cnt[i] = 0;
    if (blockIdx.x == 0 && threadIdx.x < 32) {
        int bad = 0;
        for (int j = threadIdx.x; j < 256; j += 32)
            if (e[2 * j + 1] != 0u) bad = 1;
        unsigned any = __ballot_sync(0xffffffffu, bad);
        if (threadIdx.x == 0) g_is64 = (any == 0u) ? 1 : 0;
    }
}

__global__ void k_fill(const void* __restrict__ edge) {
    int i = blockIdx.x * blockDim.x + threadIdx.x;
    if (i >= NE) return;
    int s, d;
    if (g_is64) {
        const long long* e = (const long long*)edge;
        s = (int)e[i]; d = (int)e[NE + i];
    } else {
        const int* e = (const int*)edge;
        s = e[i]; d = e[NE + i];
    }
    int pos = atomicAdd(&g_cnt[d], 1);
    if (pos < CAP) g_adj[((size_t)d << 7) + pos] = s;
}

// -------- split W into tf32 hi/lo --------
__global__ void k_wcvt(const float* __restrict__ W1l, const float* __restrict__ W1r,
                       const float* __restrict__ W2l, const float* __restrict__ W2r) {
    int i = blockIdx.x * blockDim.x + threadIdx.x;
    if (i >= 4 * 16384) return;
    int mat = i >> 14, p = i & 16383;
    const float* W = (mat == 0) ? W1l : (mat == 1) ? W1r : (mat == 2) ? W2l : W2r;
    float x = W[p];
    unsigned h = tf32_hi(x);
    float lo = x - __uint_as_float(h);
    g_Whi[i] = h;
    g_Wlo[i] = tf32_hi(lo);
}

// -------- gather: warp per node (proven) --------
__global__ __launch_bounds__(256)
void k_gather(const float* __restrict__ xext, int use_h) {
    const float4* __restrict__ X4 =
        reinterpret_cast<const float4*>(use_h ? g_h : xext);
    unsigned node = (blockIdx.x * blockDim.x + threadIdx.x) >> 5;
    int lane = threadIdx.x & 31;
    if (node >= NN) return;
    int cnt = min(g_cnt[node], CAP);
    const int* adj = g_adj + ((size_t)node << 7);
    float4 acc = make_float4(0.f, 0.f, 0.f, 0.f);
    for (int j0 = 0; j0 < cnt; j0 += 32) {
        int nb = min(32, cnt - j0);
        int src = (lane < nb) ? adj[j0 + lane] : 0;
#pragma unroll 4
        for (int t = 0; t < nb; t++) {
            int s = __shfl_sync(0xffffffffu, src, t);
            float4 v = X4[(size_t)s * 32 + lane];
            acc.x += v.x; acc.y += v.y; acc.z += v.z; acc.w += v.w;
        }
    }
    float inv = 1.0f / fmaxf((float)cnt, 1.0f);
    acc.x *= inv; acc.y *= inv; acc.z *= inv; acc.w *= inv;
    reinterpret_cast<float4*>(g_agg)[(size_t)node * 32 + lane] = acc;
}

// ==================== TF32 mma.sync GEMM ====================
// out[row,col] = sum_{k<256} A[row,k]*W[col,k]; A = [agg | X], W = [Wl | Wr].
// 128x128 block tile, 256 threads (8 warps: 4 row-bands x 2 col-bands).
// K chunked by 64; A smem hi/lo [128][68]; W smem hi/lo double-buffered [128 col][68].
// m16n8k8 tf32 MMAs, 3 terms (hh, hl, lh) into fp32 accumulators.
#define ASTR 68
#define A_HI 0
#define A_LO (128 * ASTR)                 // 8704 floats
#define W_BUF (2 * 128 * ASTR)            // 17408 floats: W buffers start
#define W_SZ (2 * 128 * ASTR)             // one W buffer = hi + lo = 17408 floats
#define GSMEM ((W_BUF + 2 * W_SZ) * 4)    // 208896 B

__device__ __forceinline__ void mma_tf32(float c[4], unsigned a0, unsigned a1,
                                         unsigned a2, unsigned a3,
                                         unsigned b0, unsigned b1) {
    asm volatile(
        "mma.sync.aligned.m16n8k8.row.col.f32.tf32.tf32.f32 "
        "{%0,%1,%2,%3}, {%4,%5,%6,%7}, {%8,%9}, {%0,%1,%2,%3};"
        : "+f"(c[0]), "+f"(c[1]), "+f"(c[2]), "+f"(c[3])
        : "r"(a0), "r"(a1), "r"(a2), "r"(a3), "r"(b0), "r"(b1));
}

__global__ __launch_bounds__(256, 1)
void k_gemm(const float* __restrict__ Xext,
            const float* __restrict__ bias,
            float* __restrict__ outext,
            int matL, int matR, int use_h_in, int use_h_out, int do_relu) {
    extern __shared__ float sm[];
    const float* __restrict__ X = use_h_in ? g_h : Xext;
    float* __restrict__ out = use_h_out ? g_h : outext;

    int tid = threadIdx.x;
    int row0 = blockIdx.x * 128;
    int wid = tid >> 5, lane = tid & 31;
    int wr = wid & 3, wc = wid >> 2;       // 4 row-bands x 2 col-bands
    int lq = lane >> 2, lr4 = lane & 3;    // frag coords

    // ---- producers ----
    int my_r = tid >> 4, my_q = tid & 15;  // A: 8 rows (stride16) x float4 col
    float4 ald[8];
    auto a_ldg = [&](int c) {
        const float* P = (c < 2) ? g_agg : X;
        int koff = (c & 1) * 64;
#pragma unroll
        for (int j = 0; j < 8; j++) {
            int row = row0 + my_r + j * 16;
            ald[j] = (row < NN)
                ? *reinterpret_cast<const float4*>(P + (size_t)row * DD + koff + my_q * 4)
                : make_float4(0.f, 0.f, 0.f, 0.f);
        }
    };
    auto a_cvt_sts = [&]() {
#pragma unroll
        for (int j = 0; j < 8; j++) {
            int r = my_r + j * 16;
            float* ph = sm + A_HI + r * ASTR + my_q * 4;
            float* pl = sm + A_LO + r * ASTR + my_q * 4;
            float xs[4] = {ald[j].x, ald[j].y, ald[j].z, ald[j].w};
            float4 h4, l4;
            float* hp = &h4.x; float* lp = &l4.x;
#pragma unroll
            for (int t = 0; t < 4; t++) {
                unsigned h = tf32_hi(xs[t]);
                hp[t] = __uint_as_float(h);
                lp[t] = __uint_as_float(tf32_hi(xs[t] - __uint_as_float(h)));
            }
            *reinterpret_cast<float4*>(ph) = h4;
            *reinterpret_cast<float4*>(pl) = l4;
        }
    };
    // W cp.async: 2 threads per col, each 32 k x {hi,lo}
    int wcol = tid >> 1, whalf = tid & 1;
    auto w_async = [&](int c) {
        int mat = (c < 2) ? matL : matR;
        int koff = (c & 1) * 64;
        int b = c & 1;
        const unsigned* srcH = g_Whi + mat * 16384 + wcol * 128 + koff + whalf * 32;
        const unsigned* srcL = g_Wlo + mat * 16384 + wcol * 128 + koff + whalf * 32;
        float* dstH = sm + W_BUF + b * W_SZ + wcol * ASTR + whalf * 32;
        float* dstL = dstH + 128 * ASTR;
#pragma unroll
        for (int t = 0; t < 8; t++) {
            unsigned sh = (unsigned)__cvta_generic_to_shared(dstH + t * 4);
            unsigned sl = (unsigned)__cvta_generic_to_shared(dstL + t * 4);
            asm volatile("cp.async.ca.shared.global [%0], [%1], 16;"
                         :: "r"(sh), "l"(srcH + t * 4));
            asm volatile("cp.async.ca.shared.global [%0], [%1], 16;"
                         :: "r"(sl), "l"(srcL + t * 4));
        }
        asm volatile("cp.async.commit_group;");
    };

    float C[2][8][4];
#pragma unroll
    for (int m = 0; m < 2; m++)
#pragma unroll
        for (int n = 0; n < 8; n++)
#pragma unroll
            for (int t = 0; t < 4; t++) C[m][n][t] = 0.f;

    // prologue: chunk 0
    a_ldg(0);
    w_async(0);
    a_cvt_sts();
    asm volatile("cp.async.wait_group 0;");
    __syncthreads();

    for (int c = 0; c < 4; c++) {
        if (c < 3) { a_ldg(c + 1); w_async(c + 1); }

        const float* Ah = sm + A_HI + (wr * 32 + lq) * ASTR + lr4;
        const float* Al = sm + A_LO + (wr * 32 + lq) * ASTR + lr4;
        const float* Wh = sm + W_BUF + (c & 1) * W_SZ + (wc * 64 + lq) * ASTR + lr4;
        const float* Wl_ = Wh + 128 * ASTR;

#pragma unroll 2
        for (int k8 = 0; k8 < 8; k8++) {
            int kb = k8 * 8;
            unsigned ah[2][4], al[2][4];
#pragma unroll
            for (int m = 0; m < 2; m++) {
                const float* p = Ah + m * 16 * ASTR + kb;
                const float* q = Al + m * 16 * ASTR + kb;
                ah[m][0] = __float_as_uint(p[0]);
                ah[m][1] = __float_as_uint(p[8 * ASTR]);
                ah[m][2] = __float_as_uint(p[4]);
                ah[m][3] = __float_as_uint(p[8 * ASTR + 4]);
                al[m][0] = __float_as_uint(q[0]);
                al[m][1] = __float_as_uint(q[8 * ASTR]);
                al[m][2] = __float_as_uint(q[4]);
                al[m][3] = __float_as_uint(q[8 * ASTR + 4]);
            }
#pragma unroll
            for (int n = 0; n < 8; n++) {
                const float* pb = Wh + n * 8 * ASTR + kb;
                const float* qb = Wl_ + n * 8 * ASTR + kb;
                unsigned bh0 = __float_as_uint(pb[0]), bh1 = __float_as_uint(pb[4]);
                unsigned bl0 = __float_as_uint(qb[0]), bl1 = __float_as_uint(qb[4]);
#pragma unroll
                for (int m = 0; m < 2; m++) {
                    mma_tf32(C[m][n], ah[m][0], ah[m][1], ah[m][2], ah[m][3], bh0, bh1);
                    mma_tf32(C[m][n], ah[m][0], ah[m][1], ah[m][2], ah[m][3], bl0, bl1);
                    mma_tf32(C[m][n], al[m][0], al[m][1], al[m][2], al[m][3], bh0, bh1);
                }
            }
        }

        if (c < 3) {
            __syncthreads();                 // A buffer consumers done
            a_cvt_sts();                     // overwrite A buffer for chunk c+1
            asm volatile("cp.async.wait_group 0;");
            __syncthreads();
        }
    }

    // ---- epilogue ----
#pragma unroll
    for (int m = 0; m < 2; m++) {
        int r0 = row0 + wr * 32 + m * 16 + lq;
#pragma unroll
        for (int n = 0; n < 8; n++) {
            int colb = wc * 64 + n * 8 + 2 * lr4;
            float2 bb = *reinterpret_cast<const float2*>(bias + colb);
            float2 v0 = make_float2(C[m][n][0] + bb.x, C[m][n][1] + bb.y);
            float2 v1 = make_float2(C[m][n][2] + bb.x, C[m][n][3] + bb.y);
            if (do_relu) {
                v0.x = fmaxf(v0.x, 0.f); v0.y = fmaxf(v0.y, 0.f);
                v1.x = fmaxf(v1.x, 0.f); v1.y = fmaxf(v1.y, 0.f);
            }
            if (r0 < NN)
                *reinterpret_cast<float2*>(out + (size_t)r0 * DD + colb) = v0;
            if (r0 + 8 < NN)
                *reinterpret_cast<float2*>(out + (size_t)(r0 + 8) * DD + colb) = v1;
        }
    }
}

extern "C" void kernel_launch(void* const* d_in, const int* in_sizes, int n_in,
                              void* d_out, int out_size) {
    const float* x   = (const float*)d_in[0];
    const void*  edg = d_in[1];
    const float* W1l = (const float*)d_in[2];
    const float* b1  = (const float*)d_in[3];
    const float* W1r = (const float*)d_in[4];
    const float* W2l = (const float*)d_in[5];
    const float* b2  = (const float*)d_in[6];
    const float* W2r = (const float*)d_in[7];
    float* out = (float*)d_out;

    cudaFuncSetAttribute(k_gemm, cudaFuncAttributeMaxDynamicSharedMemorySize, GSMEM);

    const int node_blocks = (NN + 255) / 256;
    const int edge_blocks = (NE + 255) / 256;
    const int gath_blocks = (NN * 32 + 255) / 256;
    const int gemm_blocks = (NN + 127) / 128;

    k_init<<<node_blocks, 256>>>((const unsigned int*)edg);
    k_fill<<<edge_blocks, 256>>>(edg);
    k_wcvt<<<256, 256>>>(W1l, W1r, W2l, W2r);

    // Layer 1
    k_gather<<<gath_blocks, 256>>>(x, 0);
    k_gemm<<<gemm_blocks, 256, GSMEM>>>(x, b1, out, /*matL=*/0, /*matR=*/1,
                                        /*use_h_in=*/0, /*use_h_out=*/1, /*relu=*/1);
    // Layer 2
    k_gather<<<gath_blocks, 256>>>(x, 1);
    k_gemm<<<gemm_blocks, 256, GSMEM>>>(x, b2, out, /*matL=*/2, /*matR=*/3,
                                        /*use_h_in=*/1, /*use_h_out=*/0, /*relu=*/0);
}

// round 10
// speedup vs baseline: 1.0919x; 1.0919x over previous
#include <cuda_runtime.h>
#include <cstdint>
typedef unsigned long long ull;

#define NN 100000
#define NE 1600000
#define DD 128
#define CAP 128

// -------- scratch (device globals: no allocation allowed) --------
__device__ __align__(256) float g_agg[(size_t)NN * DD];
__device__ __align__(256) float g_h[(size_t)NN * DD];
__device__ int g_cnt[NN];
__device__ int g_adj[(size_t)NN * CAP];
__device__ int g_is64;
// W in mma-fragment layout: [mat][k8 0..15][ntile 0..15][lane 0..31][bh0,bh1,bl0,bl1]
__device__ __align__(256) unsigned g_Wfrag[4 * 32768];

__device__ __forceinline__ unsigned tf32_hi(float x) {
    unsigned h; asm("cvt.rna.tf32.f32 %0, %1;" : "=r"(h) : "f"(x)); return h;
}

// -------- init: zero counts; detect edge dtype --------
__global__ void k_init(const unsigned int* __restrict__ e) {
    int i = blockIdx.x * blockDim.x + threadIdx.x;
    if (i < NN) g_cnt[i] = 0;
    if (blockIdx.x == 0 && threadIdx.x < 32) {
        int bad = 0;
        for (int j = threadIdx.x; j < 256; j += 32)
            if (e[2 * j + 1] != 0u) bad = 1;
        unsigned any = __ballot_sync(0xffffffffu, bad);
        if (threadIdx.x == 0) g_is64 = (any == 0u) ? 1 : 0;
    }
}

__global__ void k_fill(const void* __restrict__ edge) {
    int i = blockIdx.x * blockDim.x + threadIdx.x;
    if (i >= NE) return;
    int s, d;
    if (g_is64) {
        const long long* e = (const long long*)edge;
        s = (int)e[i]; d = (int)e[NE + i];
    } else {
        const int* e = (const int*)edge;
        s = e[i]; d = e[NE + i];
    }
    int pos = atomicAdd(&g_cnt[d], 1);
    if (pos < CAP) g_adj[((size_t)d << 7) + pos] = s;
}

// -------- split W into tf32 hi/lo, fragment layout --------
// thread i: mat = i>>14; idx = i&16383: wh = idx&1 (b0/b1), lane, ntile, k8
__global__ void k_wcvt(const float* __restrict__ W1l, const float* __restrict__ W1r,
                       const float* __restrict__ W2l, const float* __restrict__ W2r) {
    int i = blockIdx.x * blockDim.x + threadIdx.x;
    if (i >= 4 * 16384) return;
    int mat = i >> 14, idx = i & 16383;
    int wh = idx & 1, lane = (idx >> 1) & 31, nt = (idx >> 6) & 15, k8 = idx >> 10;
    const float* W = (mat == 0) ? W1l : (mat == 1) ? W1r : (mat == 2) ? W2l : W2r;
    int col = nt * 8 + (lane >> 2);
    int k = k8 * 8 + (lane & 3) + wh * 4;
    float x = W[col * 128 + k];
    unsigned h = tf32_hi(x);
    unsigned l = tf32_hi(x - __uint_as_float(h));
    unsigned base = mat * 32768 + ((k8 * 16 + nt) * 32 + lane) * 4;
    g_Wfrag[base + wh] = h;
    g_Wfrag[base + 2 + wh] = l;
}

// -------- gather: warp per node (proven) --------
__global__ __launch_bounds__(256)
void k_gather(const float* __restrict__ xext, int use_h) {
    const float4* __restrict__ X4 =
        reinterpret_cast<const float4*>(use_h ? g_h : xext);
    unsigned node = (blockIdx.x * blockDim.x + threadIdx.x) >> 5;
    int lane = threadIdx.x & 31;
    if (node >= NN) return;
    int cnt = min(g_cnt[node], CAP);
    const int* adj = g_adj + ((size_t)node << 7);
    float4 acc = make_float4(0.f, 0.f, 0.f, 0.f);
    for (int j0 = 0; j0 < cnt; j0 += 32) {
        int nb = min(32, cnt - j0);
        int src = (lane < nb) ? adj[j0 + lane] : 0;
#pragma unroll 4
        for (int t = 0; t < nb; t++) {
            int s = __shfl_sync(0xffffffffu, src, t);
            float4 v = X4[(size_t)s * 32 + lane];
            acc.x += v.x; acc.y += v.y; acc.z += v.z; acc.w += v.w;
        }
    }
    float inv = 1.0f / fmaxf((float)cnt, 1.0f);
    acc.x *= inv; acc.y *= inv; acc.z *= inv; acc.w *= inv;
    reinterpret_cast<float4*>(g_agg)[(size_t)node * 32 + lane] = acc;
}

// ==================== TF32 mma.sync GEMM, fragment-layout smem ====================
// A smem: AH/AL[slab = k8*8 + mtile][lane][4 words], slab 0..63. 32KB each.
// W smem: 2 buffers of [k8 0..7][ntile 0..15][lane][4 words] = 64KB each.
#define A_HI 0
#define A_LO 8192                          // floats
#define W_BUF 16384
#define W_SZ 16384
#define GSMEM ((W_BUF + 2 * W_SZ) * 4)     // 196608 B

__device__ __forceinline__ void mma_tf32(float c[4], unsigned a0, unsigned a1,
                                         unsigned a2, unsigned a3,
                                         unsigned b0, unsigned b1) {
    asm volatile(
        "mma.sync.aligned.m16n8k8.row.col.f32.tf32.tf32.f32 "
        "{%0,%1,%2,%3}, {%4,%5,%6,%7}, {%8,%9}, {%0,%1,%2,%3};"
        : "+f"(c[0]), "+f"(c[1]), "+f"(c[2]), "+f"(c[3])
        : "r"(a0), "r"(a1), "r"(a2), "r"(a3), "r"(b0), "r"(b1));
}

__global__ __launch_bounds__(256, 1)
void k_gemm(const float* __restrict__ Xext,
            const float* __restrict__ bias,
            float* __restrict__ outext,
            int matL, int matR, int use_h_in, int use_h_out, int do_relu) {
    extern __shared__ float sm[];
    const float* __restrict__ X = use_h_in ? g_h : Xext;
    float* __restrict__ out = use_h_out ? g_h : outext;

    int tid = threadIdx.x;
    int row0 = blockIdx.x * 128;
    int wid = tid >> 5, lane = tid & 31;
    int wr = wid & 3, wc = wid >> 2;       // 4 row-bands x 2 col-bands
    int lq = lane >> 2, lr4 = lane & 3;

    // ---- A producer: row-low = tid&15, float4 index = tid>>4
    int my_r = tid & 15, my_q = tid >> 4;
    float4 ald[8];
    auto a_ldg = [&](int c) {
        const float* P = (c < 2) ? g_agg : X;
        int koff = (c & 1) * 64;
#pragma unroll
        for (int j = 0; j < 8; j++) {
            int row = row0 + my_r + j * 16;
            ald[j] = (row < NN)
                ? *reinterpret_cast<const float4*>(P + (size_t)row * DD + koff + my_q * 4)
                : make_float4(0.f, 0.f, 0.f, 0.f);
        }
    };
    // fragment STS: element (r, kl=4*my_q+t) -> slab = k8*8+mtile, lane=(r&7)*4+t,
    // word = ((r>>3)&1) | ((my_q&1)<<1)
    int a_lane = (my_r & 7) * 4;
    int a_word = ((my_r >> 3) & 1) | ((my_q & 1) << 1);
    int a_k8 = my_q >> 1;
    auto a_cvt_sts = [&]() {
#pragma unroll
        for (int j = 0; j < 8; j++) {
            int slab = a_k8 * 8 + j;
            float* ph = sm + A_HI + (slab * 32 + a_lane) * 4 + a_word;
            float* pl = sm + A_LO + (slab * 32 + a_lane) * 4 + a_word;
            float xs[4] = {ald[j].x, ald[j].y, ald[j].z, ald[j].w};
#pragma unroll
            for (int t = 0; t < 4; t++) {
                unsigned h = tf32_hi(xs[t]);
                ph[t * 4] = __uint_as_float(h);
                pl[t * 4] = __uint_as_float(tf32_hi(xs[t] - __uint_as_float(h)));
            }
        }
    };
    // ---- W producer: contiguous cp.async, 16 x 16B per thread
    auto w_async = [&](int c) {
        int mat = (c < 2) ? matL : matR;
        const unsigned* src = g_Wfrag + mat * 32768 + (c & 1) * 16384 + tid * 64;
        float* dst = sm + W_BUF + (c & 1) * W_SZ + tid * 64;
#pragma unroll
        for (int t = 0; t < 16; t++) {
            unsigned sa = (unsigned)__cvta_generic_to_shared(dst + t * 4);
            asm volatile("cp.async.ca.shared.global [%0], [%1], 16;"
                         :: "r"(sa), "l"(src + t * 4));
        }
        asm volatile("cp.async.commit_group;");
    };

    float C[2][8][4];
#pragma unroll
    for (int m = 0; m < 2; m++)
#pragma unroll
        for (int n = 0; n < 8; n++)
#pragma unroll
            for (int t = 0; t < 4; t++) C[m][n][t] = 0.f;

    a_ldg(0);
    w_async(0);
    a_cvt_sts();
    asm volatile("cp.async.wait_group 0;");
    __syncthreads();

    for (int c = 0; c < 4; c++) {
        if (c < 3) { a_ldg(c + 1); w_async(c + 1); }

        const float* AH = sm + A_HI + (wr * 2 * 32 + lane) * 4;   // + k8*8*128, m*128
        const float* AL = sm + A_LO + (wr * 2 * 32 + lane) * 4;
        const float* WB = sm + W_BUF + (c & 1) * W_SZ + ((wc * 8) * 32 + lane) * 4;

#pragma unroll
        for (int k8 = 0; k8 < 8; k8++) {
            float4 ah[2], al[2];
#pragma unroll
            for (int m = 0; m < 2; m++) {
                ah[m] = *reinterpret_cast<const float4*>(AH + (k8 * 8 + m) * 128);
                al[m] = *reinterpret_cast<const float4*>(AL + (k8 * 8 + m) * 128);
            }
#pragma unroll
            for (int n = 0; n < 8; n++) {
                float4 b = *reinterpret_cast<const float4*>(WB + (k8 * 16 + n) * 128);
                unsigned bh0 = __float_as_uint(b.x), bh1 = __float_as_uint(b.y);
                unsigned bl0 = __float_as_uint(b.z), bl1 = __float_as_uint(b.w);
#pragma unroll
                for (int m = 0; m < 2; m++) {
                    unsigned a0 = __float_as_uint(ah[m].x), a1 = __float_as_uint(ah[m].y);
                    unsigned a2 = __float_as_uint(ah[m].z), a3 = __float_as_uint(ah[m].w);
                    mma_tf32(C[m][n], a0, a1, a2, a3, bh0, bh1);
                    mma_tf32(C[m][n], a0, a1, a2, a3, bl0, bl1);
                    mma_tf32(C[m][n], __float_as_uint(al[m].x), __float_as_uint(al[m].y),
                             __float_as_uint(al[m].z), __float_as_uint(al[m].w), bh0, bh1);
                }
            }
        }

        if (c < 3) {
            __syncthreads();
            a_cvt_sts();
            asm volatile("cp.async.wait_group 0;");
            __syncthreads();
        }
    }

    // ---- epilogue (identical mapping to R9, which verified) ----
#pragma unroll
    for (int m = 0; m < 2; m++) {
        int r0 = row0 + wr * 32 + m * 16 + lq;
#pragma unroll
        for (int n = 0; n < 8; n++) {
            int colb = wc * 64 + n * 8 + 2 * lr4;
            float2 bb = *reinterpret_cast<const float2*>(bias + colb);
            float2 v0 = make_float2(C[m][n][0] + bb.x, C[m][n][1] + bb.y);
            float2 v1 = make_float2(C[m][n][2] + bb.x, C[m][n][3] + bb.y);
            if (do_relu) {
                v0.x = fmaxf(v0.x, 0.f); v0.y = fmaxf(v0.y, 0.f);
                v1.x = fmaxf(v1.x, 0.f); v1.y = fmaxf(v1.y, 0.f);
            }
            if (r0 < NN)
                *reinterpret_cast<float2*>(out + (size_t)r0 * DD + colb) = v0;
            if (r0 + 8 < NN)
                *reinterpret_cast<float2*>(out + (size_t)(r0 + 8) * DD + colb) = v1;
        }
    }
}

extern "C" void kernel_launch(void* const* d_in, const int* in_sizes, int n_in,
                              void* d_out, int out_size) {
    const float* x   = (const float*)d_in[0];
    const void*  edg = d_in[1];
    const float* W1l = (const float*)d_in[2];
    const float* b1  = (const float*)d_in[3];
    const float* W1r = (const float*)d_in[4];
    const float* W2l = (const float*)d_in[5];
    const float* b2  = (const float*)d_in[6];
    const float* W2r = (const float*)d_in[7];
    float* out = (float*)d_out;

    cudaFuncSetAttribute(k_gemm, cudaFuncAttributeMaxDynamicSharedMemorySize, GSMEM);

    const int node_blocks = (NN + 255) / 256;
    const int edge_blocks = (NE + 255) / 256;
    const int gath_blocks = (NN * 32 + 255) / 256;
    const int gemm_blocks = (NN + 127) / 128;

    k_init<<<node_blocks, 256>>>((const unsigned int*)edg);
    k_fill<<<edge_blocks, 256>>>(edg);
    k_wcvt<<<256, 256>>>(W1l, W1r, W2l, W2r);

    // Layer 1
    k_gather<<<gath_blocks, 256>>>(x, 0);
    k_gemm<<<gemm_blocks, 256, GSMEM>>>(x, b1, out, 0, 1, 0, 1, 1);
    // Layer 2
    k_gather<<<gath_blocks, 256>>>(x, 1);
    k_gemm<<<gemm_blocks, 256, GSMEM>>>(x, b2, out, 2, 3, 1, 0, 0);
}